// round 13
// baseline (speedup 1.0000x reference)
#include <cuda_runtime.h>
#include <cstdint>
#include <math.h>

#define BB   8
#define NN   4096
#define HID  64
#define JJ   128
#define CAP  96
#define NROWS (BB*NN)   // 32768

#define K1R   8                 // rows per k1 block
#define K1BLK (NROWS / K1R)     // 4096 k1 blocks (512 per batch)
#define NPB   64                // nodes per k2 block
#define K2BLK (NROWS / NPB)     // 512 k2 blocks (64 per batch)
#define BATCH 16

// ---- scratch (device globals; no allocation allowed) ----
__device__ int   g_cnt[NROWS];
__device__ int   g_idx[(size_t)NROWS * CAP];   // packed: col | (val==2 ? 0x80000000 : 0)
__device__ float g_h1[(size_t)NROWS * HID];    // 8 MB
__device__ float g_h2[(size_t)NROWS * HID];    // 8 MB
__device__ float g_gge[BB * HID];              // global graph embedding accumulator
__device__ float g_scores[BB * JJ];            // actor scores before softmax
__device__ int   g_done[BB];                   // k3 per-batch ticket counters
__device__ int   g_b_done[BB];                 // k1 blocks finished per batch
__device__ int   g_k2_pass[BB];                // k2 blocks past spin per batch

__device__ __forceinline__ void cp_async16(void* smem_dst, const void* gmem_src) {
    unsigned sa = (unsigned)__cvta_generic_to_shared(smem_dst);
    asm volatile("cp.async.cg.shared.global [%0], [%1], 16;\n"
                 :: "r"(sa), "l"(gmem_src));
}
__device__ __forceinline__ void cp_commit() {
    asm volatile("cp.async.commit_group;\n");
}
template <int N>
__device__ __forceinline__ void cp_wait() {
    asm volatile("cp.async.wait_group %0;\n" :: "n"(N));
}
__device__ __forceinline__ float tanh_fast(float x) {
    float r;
    asm("tanh.approx.f32 %0, %1;" : "=f"(r) : "f"(x));
    return r;
}

// ---- shared-memory layouts (union'd inside the mega kernel) ----
#define NBUF 3
#define NCHUNK 32
struct SmemK1 {
    float w2[HID * HID];          // 16 KB
    uint4 buf[K1R][NBUF][32];     // 12 KB
    float w1[2 * HID];
    float b1[HID], b2[HID];
    float p[K1R][2];
    float z[K1R][HID];
    int   cnt[K1R];
};
struct SmemK2 {
    float x[NPB][HID];            // 16 KB
    float part[4][BATCH][HID];    // 16 KB
    float z[BATCH][HID];          // 4 KB
    float acc[HID];
};
static constexpr size_t SMEM_MAX =
    sizeof(SmemK1) > sizeof(SmemK2) ? sizeof(SmemK1) : sizeof(SmemK2);

// ============================================================================
// k1 body: stream one 8-row stripe of adj via per-warp cp.async ring,
// shared-atomic compaction + GIN0 MLP. Release-increments g_b_done[batch].
// ============================================================================
__device__ __forceinline__ void k1_body(
    char* smraw,
    const float* __restrict__ adj, const float* __restrict__ feat,
    const float* __restrict__ w1, const float* __restrict__ b1,
    const float* __restrict__ w2, const float* __restrict__ b2)
{
    SmemK1& s = *reinterpret_cast<SmemK1*>(smraw);
    const int tid  = threadIdx.x;
    const int w    = tid >> 5;
    const int lane = tid & 31;

    for (int i = tid; i < HID * HID; i += 256) s.w2[i] = w2[i];
    if (tid < 2 * HID) s.w1[tid] = w1[tid];
    if (tid < HID) { s.b1[tid] = b1[tid]; s.b2[tid] = b2[tid]; }
    if (lane == 0) s.cnt[w] = 0;
    if (blockIdx.x == 0) {               // zero accumulators (block 0 retires
        for (int i = tid; i < BB * HID; i += 256) g_gge[i] = 0.f;   // before any
        if (tid < BB) g_done[tid] = 0;                              // k2 passes)
    }
    __syncwarp();

    const int r = blockIdx.x * K1R + w;
    const int b = r >> 12;
    const float* __restrict__ grow = adj + (size_t)r * NN;
    const float2* __restrict__ f2p = (const float2*)feat + (size_t)b * NN;
    int* __restrict__ irow = g_idx + (size_t)r * CAP;

    float p0 = 0.f, p1 = 0.f;

#define PROC_ELEM(bits, jj) do {                                           \
        if ((bits) != 0u) {                                                \
            const int pos = atomicAdd(&s.cnt[w], 1);                       \
            const bool two = ((bits) == 0x40000000u);                      \
            if (pos < CAP) irow[pos] = (jj) | (two ? 0x80000000 : 0);      \
            const float2 f = f2p[(jj)];                                    \
            const float sv = two ? 2.f : 1.f;                              \
            p0 += sv * f.x; p1 += sv * f.y;                                \
        }                                                                  \
    } while (0)

#define PROC_CHUNK(c) do {                                                 \
        const uint4 v = s.buf[w][(c) % NBUF][lane];                        \
        if (v.x | v.y | v.z | v.w) {                                       \
            const int jb = (c) * 128 + lane * 4;                           \
            PROC_ELEM(v.x, jb + 0);                                        \
            PROC_ELEM(v.y, jb + 1);                                        \
            PROC_ELEM(v.z, jb + 2);                                        \
            PROC_ELEM(v.w, jb + 3);                                        \
        }                                                                  \
    } while (0)

    #pragma unroll
    for (int c = 0; c < NBUF; c++) {
        cp_async16(&s.buf[w][c][lane], grow + c * 128 + lane * 4);
        cp_commit();
    }
    #pragma unroll 1
    for (int c = 0; c < NCHUNK - NBUF; c++) {
        cp_wait<NBUF - 1>();
        PROC_CHUNK(c);
        cp_async16(&s.buf[w][(c + NBUF) % NBUF][lane],
                   grow + (c + NBUF) * 128 + lane * 4);
        cp_commit();
    }
    cp_wait<0>();
    #pragma unroll
    for (int c = NCHUNK - NBUF; c < NCHUNK; c++) PROC_CHUNK(c);
#undef PROC_CHUNK
#undef PROC_ELEM

    #pragma unroll
    for (int o = 16; o > 0; o >>= 1) {
        p0 += __shfl_down_sync(0xffffffffu, p0, o);
        p1 += __shfl_down_sync(0xffffffffu, p1, o);
    }
    __syncwarp();
    if (lane == 0) {
        s.p[w][0] = p0; s.p[w][1] = p1;
        g_cnt[r] = min(s.cnt[w], CAP);
    }
    __syncthreads();

    // GIN0 MLP for the 8 rows (2 -> 64 relu -> 64 relu)
    const int h = tid & 63;
    const int slot = tid >> 6;           // 0..3
    #pragma unroll
    for (int t = 0; t < 2; t++) {
        const int rr = slot + t * 4;
        const float z = s.b1[h] + s.p[rr][0] * s.w1[h] + s.p[rr][1] * s.w1[HID + h];
        s.z[rr][h] = fmaxf(z, 0.f);
    }
    __syncthreads();
    #pragma unroll
    for (int t = 0; t < 2; t++) {
        const int rr = slot + t * 4;
        float acc = s.b2[h];
        #pragma unroll
        for (int k = 0; k < HID; k++) acc += s.z[rr][k] * s.w2[k * HID + h];
        g_h1[(size_t)(blockIdx.x * K1R + rr) * HID + h] = fmaxf(acc, 0.f);
    }

    // release: this stripe (incl. g_h1/g_cnt/g_idx) is done
    __syncthreads();
    if (tid == 0) {
        __threadfence();
        atomicAdd(&g_b_done[blockIdx.x >> 9], 1);   // 512 k1 blocks per batch
    }
}

// ============================================================================
// k2 body: spin until this batch's 512 k1 blocks are done, then fused
// gather + register-stationary GIN1 MLP + graph pooling. Self-resets counters.
// ============================================================================
__device__ __forceinline__ void k2_body(
    char* smraw,
    const float* __restrict__ w1, const float* __restrict__ b1,
    const float* __restrict__ w2, const float* __restrict__ b2,
    const float* __restrict__ gp)
{
    SmemK2& s = *reinterpret_cast<SmemK2*>(smraw);
    const int tid  = threadIdx.x;
    const int h    = tid & 63;
    const int fg   = tid >> 6;
    const int wid  = tid >> 5, lane = tid & 31;
    const int base = (blockIdx.x - K1BLK) * NPB;
    const int b    = base >> 12;

    // acquire: wait for this batch's k1 stripes
    if (tid == 0) {
        while (*(volatile int*)&g_b_done[b] < 512) __nanosleep(128);
        __threadfence();
        const int p = atomicAdd(&g_k2_pass[b], 1);
        if (p == 63) { g_b_done[b] = 0; g_k2_pass[b] = 0; }  // reset for next call
    }
    __syncthreads();

    const float2* __restrict__ h1v = (const float2*)g_h1 + ((size_t)b << 12) * 32;
    if (tid < HID) s.acc[tid] = 0.f;

    // Phase A: gather 64 nodes (two passes of 8 warps x 4 nodes interleaved)
    #pragma unroll 1
    for (int pass = 0; pass < 2; pass++) {
        const int ln0 = wid * 4 + pass * 32;
        int cnt[4]; const int* ip[4];
        #pragma unroll
        for (int i = 0; i < 4; i++) {
            cnt[i] = g_cnt[base + ln0 + i];
            ip[i]  = g_idx + (size_t)(base + ln0 + i) * CAP;
        }
        float ax[4] = {0.f, 0.f, 0.f, 0.f}, ay[4] = {0.f, 0.f, 0.f, 0.f};
        const int maxc = max(max(cnt[0], cnt[1]), max(cnt[2], cnt[3]));
        for (int k0 = 0; k0 < maxc; k0 += 32) {
            int enc[4];
            #pragma unroll
            for (int i = 0; i < 4; i++)
                enc[i] = (k0 + lane < cnt[i]) ? ip[i][k0 + lane] : 0;
            const int rem = min(maxc - k0, 32);
            #pragma unroll 2
            for (int n = 0; n < rem; n++) {
                #pragma unroll
                for (int i = 0; i < 4; i++) {
                    const int e = __shfl_sync(0xffffffffu, enc[i], n);
                    if (k0 + n < cnt[i]) {       // warp-uniform predicate
                        const float2 v = h1v[(size_t)(e & 0x7fffffff) * 32 + lane];
                        const float sv = (e < 0) ? 2.f : 1.f;
                        ax[i] += sv * v.x; ay[i] += sv * v.y;
                    }
                }
            }
        }
        #pragma unroll
        for (int i = 0; i < 4; i++)
            *(float2*)&s.x[ln0 + i][2 * lane] = make_float2(ax[i], ay[i]);
    }

    // register-stationary weight slices
    float w1r[16], w2r[16];
    #pragma unroll
    for (int i = 0; i < 16; i++) {
        w1r[i] = w1[(fg * 16 + i) * HID + h];
        w2r[i] = w2[(fg * 16 + i) * HID + h];
    }
    __syncthreads();

    float gacc = 0.f;
    #pragma unroll 1
    for (int nb = 0; nb < 4; nb++) {
        const int n0 = nb * BATCH;

        #pragma unroll
        for (int n = 0; n < BATCH; n++) {
            float a = 0.f;
            #pragma unroll
            for (int q = 0; q < 4; q++) {
                const float4 xv = *(const float4*)&s.x[n0 + n][fg * 16 + q * 4];
                a += xv.x * w1r[q * 4] + xv.y * w1r[q * 4 + 1]
                   + xv.z * w1r[q * 4 + 2] + xv.w * w1r[q * 4 + 3];
            }
            s.part[fg][n][h] = a;
        }
        __syncthreads();

        #pragma unroll
        for (int k = 0; k < 4; k++) {
            const int p = tid + 256 * k;
            const int n = p >> 6, hh = p & 63;
            const float z = b1[hh] + ((s.part[0][n][hh] + s.part[1][n][hh])
                                    + (s.part[2][n][hh] + s.part[3][n][hh]));
            s.z[n][hh] = fmaxf(z, 0.f);
        }
        __syncthreads();

        #pragma unroll
        for (int n = 0; n < BATCH; n++) {
            float a = 0.f;
            #pragma unroll
            for (int q = 0; q < 4; q++) {
                const float4 zv = *(const float4*)&s.z[n][fg * 16 + q * 4];
                a += zv.x * w2r[q * 4] + zv.y * w2r[q * 4 + 1]
                   + zv.z * w2r[q * 4 + 2] + zv.w * w2r[q * 4 + 3];
            }
            s.part[fg][n][h] = a;
        }
        __syncthreads();

        #pragma unroll
        for (int k = 0; k < 4; k++) {
            const int p = tid + 256 * k;
            const int n = p >> 6, hh = p & 63;
            float v = b2[hh] + ((s.part[0][n][hh] + s.part[1][n][hh])
                              + (s.part[2][n][hh] + s.part[3][n][hh]));
            v = fmaxf(v, 0.f);
            g_h2[(size_t)(base + n0 + n) * HID + hh] = v;
            gacc += gp[base + n0 + n] * v;     // hh == h for all k
        }
        __syncthreads();
    }
    atomicAdd(&s.acc[h], gacc);
    __syncthreads();
    if (tid < HID) atomicAdd(&g_gge[b * HID + tid], s.acc[tid]);
}

// ============================================================================
// Mega kernel: blocks [0,4096) = k1 stripes; [4096,4608) = k2 tiles which
// spin on per-batch counters (scheduled last -> overlap with k1's tail).
// ============================================================================
__global__ __launch_bounds__(256, 4) void mega(
    const float* __restrict__ adj, const float* __restrict__ feat,
    const float* __restrict__ a_w1, const float* __restrict__ a_b1,
    const float* __restrict__ a_w2, const float* __restrict__ a_b2,
    const float* __restrict__ c_w1, const float* __restrict__ c_b1,
    const float* __restrict__ c_w2, const float* __restrict__ c_b2,
    const float* __restrict__ gp)
{
    __shared__ __align__(16) char smraw[SMEM_MAX];
    if (blockIdx.x < K1BLK)
        k1_body(smraw, adj, feat, a_w1, a_b1, a_w2, a_b2);
    else
        k2_body(smraw, c_w1, c_b1, c_w2, c_b2, gp);
}

// ============================================================================
// Kernel 3 (unchanged from R11): actor MLP + ticket softmax.
// ============================================================================
#define JPB 8
#define XS  66
__global__ __launch_bounds__(256) void k3_actor(
    const int* __restrict__ cand, const int* __restrict__ mask,
    const float* __restrict__ pmi,
    const float* __restrict__ w1, const float* __restrict__ b1,
    const float* __restrict__ w2, const float* __restrict__ b2,
    const float* __restrict__ w3, const float* __restrict__ b3,
    float* __restrict__ out)
{
    __shared__ __align__(16) float s_w1[HID * HID];
    __shared__ __align__(16) float s_w2[HID * HID];
    __shared__ __align__(16) float s_x[JPB * XS];
    __shared__ float s_bp[4][HID];
    __shared__ float s_base[HID];
    __shared__ float s_red[JJ];
    __shared__ int   s_ticket;

    const int tid  = threadIdx.x;
    const int bb   = blockIdx.x >> 4;
    const int jb0  = (blockIdx.x & 15) * JPB;
    const int job  = tid >> 5;
    const int lane = tid & 31;
    const int h0   = lane * 2;

    {
        const float4* w1v = (const float4*)w1;
        const float4* w2v = (const float4*)w2;
        float4* d1 = (float4*)s_w1; float4* d2 = (float4*)s_w2;
        #pragma unroll
        for (int i = 0; i < 4; i++) {
            cp_async16(&d1[tid + 256 * i], &w1v[tid + 256 * i]);
            cp_async16(&d2[tid + 256 * i], &w2v[tid + 256 * i]);
        }
        cp_commit();
    }

    {
        const int q = tid >> 6, h = tid & 63;
        const float* xs = (q < 2) ? (g_gge + bb * HID) : pmi;
        const int f0 = (q & 1) * 32;
        const int row0 = 64 + (q >> 1) * 64 + f0;
        float a = 0.f;
        #pragma unroll 8
        for (int i = 0; i < 32; i++)
            a += xs[f0 + i] * w1[(row0 + i) * HID + h];
        s_bp[q][h] = a;
    }

    {
        const int c = cand[bb * JJ + jb0 + job];
        const float2* e2 = (const float2*)(g_h2 + ((size_t)bb * NN + c) * HID);
        *(float2*)&s_x[job * XS + h0] = e2[lane];
    }
    if (tid == 0) s_ticket = -1;
    cp_wait<0>();
    __syncthreads();

    if (tid < HID)
        s_base[tid] = b1[tid] + ((s_bp[0][tid] + s_bp[1][tid])
                               + (s_bp[2][tid] + s_bp[3][tid]));
    __syncthreads();

    float a0 = s_base[h0], a1 = s_base[h0 + 1];
    #pragma unroll 16
    for (int f = 0; f < HID; f++) {
        const float xv = s_x[job * XS + f];
        const float2 wv = *(const float2*)&s_w1[f * HID + h0];
        a0 += xv * wv.x; a1 += xv * wv.y;
    }
    __syncthreads();
    s_x[job * XS + h0]     = tanh_fast(a0);
    s_x[job * XS + h0 + 1] = tanh_fast(a1);
    __syncthreads();

    a0 = b2[h0]; a1 = b2[h0 + 1];
    #pragma unroll 16
    for (int f = 0; f < HID; f++) {
        const float tv = s_x[job * XS + f];
        const float2 wv = *(const float2*)&s_w2[f * HID + h0];
        a0 += tv * wv.x; a1 += tv * wv.y;
    }

    float part = tanh_fast(a0) * w3[h0] + tanh_fast(a1) * w3[h0 + 1];
    #pragma unroll
    for (int o = 16; o > 0; o >>= 1)
        part += __shfl_down_sync(0xffffffffu, part, o);
    if (lane == 0) {
        const int jg = jb0 + job;
        float score = (part + b3[0]) * 10.0f;
        if (mask[bb * JJ + jg]) score = -INFINITY;
        g_scores[bb * JJ + jg] = score;
        __threadfence();
    }
    __syncthreads();
    if (tid == 0) s_ticket = atomicAdd(&g_done[bb], 1);
    __syncthreads();

    if (s_ticket == 15) {
        __threadfence();
        const float sc = (tid < JJ) ? __ldcg(&g_scores[bb * JJ + tid]) : -INFINITY;
        if (tid < JJ) s_red[tid] = sc;
        __syncthreads();
        for (int s = JJ / 2; s > 0; s >>= 1) {
            if (tid < s) s_red[tid] = fmaxf(s_red[tid], s_red[tid + s]);
            __syncthreads();
        }
        const float mx = s_red[0]; __syncthreads();
        const float e = (tid < JJ) ? expf(sc - mx) : 0.f;
        if (tid < JJ) s_red[tid] = e;
        __syncthreads();
        for (int s = JJ / 2; s > 0; s >>= 1) {
            if (tid < s) s_red[tid] += s_red[tid + s];
            __syncthreads();
        }
        if (tid < JJ) out[bb * JJ + tid] = e / s_red[0];
    }
}

// ============================================================================
extern "C" void kernel_launch(void* const* d_in, const int* in_sizes, int n_in,
                              void* d_out, int out_size)
{
    const float* features   = (const float*)d_in[0];
    const float* graph_pool = (const float*)d_in[1];
    const float* adj        = (const float*)d_in[2];
    const int*   candidate  = (const int*)d_in[3];
    const int*   mask       = (const int*)d_in[4];
    const float* g0w1 = (const float*)d_in[5];
    const float* g0b1 = (const float*)d_in[6];
    const float* g0w2 = (const float*)d_in[7];
    const float* g0b2 = (const float*)d_in[8];
    const float* g1w1 = (const float*)d_in[9];
    const float* g1b1 = (const float*)d_in[10];
    const float* g1w2 = (const float*)d_in[11];
    const float* g1b2 = (const float*)d_in[12];
    const float* pmi  = (const float*)d_in[13];
    const float* aw1  = (const float*)d_in[14];
    const float* ab1  = (const float*)d_in[15];
    const float* aw2  = (const float*)d_in[16];
    const float* ab2  = (const float*)d_in[17];
    const float* aw3  = (const float*)d_in[18];
    const float* ab3  = (const float*)d_in[19];
    float* out = (float*)d_out;

    mega<<<K1BLK + K2BLK, 256>>>(adj, features,
                                 g0w1, g0b1, g0w2, g0b2,
                                 g1w1, g1b1, g1w2, g1b2, graph_pool);
    k3_actor<<<BB * JJ / JPB, 256>>>(candidate, mask, pmi,
                                     aw1, ab1, aw2, ab2, aw3, ab3, out);
}

// round 16
// speedup vs baseline: 1.1397x; 1.1397x over previous
#include <cuda_runtime.h>
#include <cstdint>
#include <math.h>

#define BB   8
#define NN   4096
#define HID  64
#define JJ   128
#define CAP  96
#define NROWS (BB*NN)   // 32768

// ---- scratch (device globals; no allocation allowed) ----
__device__ int   g_cnt[NROWS];
__device__ int   g_idx[(size_t)NROWS * CAP];   // packed: col | (val==2 ? 0x80000000 : 0)
__device__ float g_h1[(size_t)NROWS * HID];    // 8 MB
__device__ float g_h2[(size_t)NROWS * HID];    // 8 MB
__device__ float g_gge[BB * HID];              // global graph embedding accumulator
__device__ float g_scores[BB * JJ];            // actor scores before softmax
__device__ int   g_done[BB];                   // per-batch completion counters

__device__ __forceinline__ void cp_async16(void* smem_dst, const void* gmem_src) {
    unsigned sa = (unsigned)__cvta_generic_to_shared(smem_dst);
    asm volatile("cp.async.cg.shared.global [%0], [%1], 16;\n"
                 :: "r"(sa), "l"(gmem_src));
}
__device__ __forceinline__ void cp_commit() {
    asm volatile("cp.async.commit_group;\n");
}
template <int N>
__device__ __forceinline__ void cp_wait() {
    asm volatile("cp.async.wait_group %0;\n" :: "n"(N));
}
__device__ __forceinline__ float tanh_fast(float x) {
    float r;
    asm("tanh.approx.f32 %0, %1;" : "=f"(r) : "f"(x));
    return r;
}

// ============================================================================
// Kernel 1 (R11 config, at HBM wall): stream adj once via per-warp cp.async
// ring. Warp-per-row, group-skip, shared-atomic compaction + GIN0 MLP.
// 16 rows / 512-thread block.
// ============================================================================
#define NBUF 3
#define NCHUNK 32
__global__ __launch_bounds__(512) void k1_scan(
    const float* __restrict__ adj, const float* __restrict__ feat,
    const float* __restrict__ w1, const float* __restrict__ b1,
    const float* __restrict__ w2, const float* __restrict__ b2)
{
    __shared__ float s_w2[HID * HID];
    __shared__ uint4 s_buf[16][NBUF][32];
    __shared__ float s_w1[2 * HID];
    __shared__ float s_b1[HID], s_b2[HID];
    __shared__ float s_p[16][2];
    __shared__ float s_z[16][HID];
    __shared__ int   s_cnt[16];

    const int tid  = threadIdx.x;
    const int w    = tid >> 5;
    const int lane = tid & 31;

    for (int i = tid; i < HID * HID; i += 512) s_w2[i] = w2[i];
    if (tid < 2 * HID) s_w1[tid] = w1[tid];
    if (tid < HID) { s_b1[tid] = b1[tid]; s_b2[tid] = b2[tid]; }
    if (lane == 0) s_cnt[w] = 0;
    if (blockIdx.x == 0) {
        if (tid < BB * HID) g_gge[tid] = 0.f;
        if (tid < BB) g_done[tid] = 0;
    }
    __syncwarp();

    const int r = blockIdx.x * 16 + w;
    const int b = r >> 12;
    const float* __restrict__ grow = adj + (size_t)r * NN;
    const float2* __restrict__ f2p = (const float2*)feat + (size_t)b * NN;
    int* __restrict__ irow = g_idx + (size_t)r * CAP;

    float p0 = 0.f, p1 = 0.f;

#define PROC_ELEM(bits, jj) do {                                           \
        if ((bits) != 0u) {                                                \
            const int pos = atomicAdd(&s_cnt[w], 1);                       \
            const bool two = ((bits) == 0x40000000u);                      \
            if (pos < CAP) irow[pos] = (jj) | (two ? 0x80000000 : 0);      \
            const float2 f = f2p[(jj)];                                    \
            const float sv = two ? 2.f : 1.f;                              \
            p0 += sv * f.x; p1 += sv * f.y;                                \
        }                                                                  \
    } while (0)

#define PROC_CHUNK(c) do {                                                 \
        const uint4 v = s_buf[w][(c) % NBUF][lane];                        \
        if (v.x | v.y | v.z | v.w) {                                       \
            const int jb = (c) * 128 + lane * 4;                           \
            PROC_ELEM(v.x, jb + 0);                                        \
            PROC_ELEM(v.y, jb + 1);                                        \
            PROC_ELEM(v.z, jb + 2);                                        \
            PROC_ELEM(v.w, jb + 3);                                        \
        }                                                                  \
    } while (0)

    #pragma unroll
    for (int c = 0; c < NBUF; c++) {
        cp_async16(&s_buf[w][c][lane], grow + c * 128 + lane * 4);
        cp_commit();
    }
    #pragma unroll 1
    for (int c = 0; c < NCHUNK - NBUF; c++) {
        cp_wait<NBUF - 1>();
        PROC_CHUNK(c);
        cp_async16(&s_buf[w][(c + NBUF) % NBUF][lane],
                   grow + (c + NBUF) * 128 + lane * 4);
        cp_commit();
    }
    cp_wait<0>();
    #pragma unroll
    for (int c = NCHUNK - NBUF; c < NCHUNK; c++) PROC_CHUNK(c);
#undef PROC_CHUNK
#undef PROC_ELEM

    #pragma unroll
    for (int o = 16; o > 0; o >>= 1) {
        p0 += __shfl_down_sync(0xffffffffu, p0, o);
        p1 += __shfl_down_sync(0xffffffffu, p1, o);
    }
    __syncwarp();
    if (lane == 0) {
        s_p[w][0] = p0; s_p[w][1] = p1;
        g_cnt[r] = min(s_cnt[w], CAP);
    }
    __syncthreads();

    const int h = tid & 63;
    const int slot = tid >> 6;
    #pragma unroll
    for (int t = 0; t < 2; t++) {
        const int rr = slot + t * 8;
        const float z = s_b1[h] + s_p[rr][0] * s_w1[h] + s_p[rr][1] * s_w1[HID + h];
        s_z[rr][h] = fmaxf(z, 0.f);
    }
    __syncthreads();
    #pragma unroll
    for (int t = 0; t < 2; t++) {
        const int rr = slot + t * 8;
        float acc = s_b2[h];
        #pragma unroll
        for (int k = 0; k < HID; k++) acc += s_z[rr][k] * s_w2[k * HID + h];
        g_h1[(size_t)(blockIdx.x * 16 + rr) * HID + h] = fmaxf(acc, 0.f);
    }
}

// ============================================================================
// Kernel 2 (R11, unchanged): fused gather + register-stationary GIN1 MLP
// + graph pooling. 64 nodes / 256-thread block (512 blocks).
// ============================================================================
#define NPB 64
#define BATCH 16
__global__ __launch_bounds__(256) void k2_fused(
    const float* __restrict__ w1, const float* __restrict__ b1,
    const float* __restrict__ w2, const float* __restrict__ b2,
    const float* __restrict__ gp)
{
    __shared__ __align__(16) float s_x[NPB][HID];          // 16 KB
    __shared__ __align__(16) float s_part[4][BATCH][HID];  // 16 KB
    __shared__ __align__(16) float s_z[BATCH][HID];        // 4 KB
    __shared__ float s_acc[HID];

    const int tid  = threadIdx.x;
    const int h    = tid & 63;
    const int fg   = tid >> 6;
    const int wid  = tid >> 5, lane = tid & 31;
    const int base = blockIdx.x * NPB;
    const int b    = base >> 12;
    const float2* __restrict__ h1v = (const float2*)g_h1 + ((size_t)b << 12) * 32;

    if (tid < HID) s_acc[tid] = 0.f;

    #pragma unroll 1
    for (int pass = 0; pass < 2; pass++) {
        const int ln0 = wid * 4 + pass * 32;
        int cnt[4]; const int* ip[4];
        #pragma unroll
        for (int i = 0; i < 4; i++) {
            cnt[i] = g_cnt[base + ln0 + i];
            ip[i]  = g_idx + (size_t)(base + ln0 + i) * CAP;
        }
        float ax[4] = {0.f, 0.f, 0.f, 0.f}, ay[4] = {0.f, 0.f, 0.f, 0.f};
        const int maxc = max(max(cnt[0], cnt[1]), max(cnt[2], cnt[3]));
        for (int k0 = 0; k0 < maxc; k0 += 32) {
            int enc[4];
            #pragma unroll
            for (int i = 0; i < 4; i++)
                enc[i] = (k0 + lane < cnt[i]) ? ip[i][k0 + lane] : 0;
            const int rem = min(maxc - k0, 32);
            #pragma unroll 2
            for (int n = 0; n < rem; n++) {
                #pragma unroll
                for (int i = 0; i < 4; i++) {
                    const int e = __shfl_sync(0xffffffffu, enc[i], n);
                    if (k0 + n < cnt[i]) {       // warp-uniform predicate
                        const float2 v = h1v[(size_t)(e & 0x7fffffff) * 32 + lane];
                        const float s = (e < 0) ? 2.f : 1.f;
                        ax[i] += s * v.x; ay[i] += s * v.y;
                    }
                }
            }
        }
        #pragma unroll
        for (int i = 0; i < 4; i++)
            *(float2*)&s_x[ln0 + i][2 * lane] = make_float2(ax[i], ay[i]);
    }

    float w1r[16], w2r[16];
    #pragma unroll
    for (int i = 0; i < 16; i++) {
        w1r[i] = w1[(fg * 16 + i) * HID + h];
        w2r[i] = w2[(fg * 16 + i) * HID + h];
    }
    __syncthreads();

    float gacc = 0.f;
    #pragma unroll 1
    for (int nb = 0; nb < 4; nb++) {
        const int n0 = nb * BATCH;

        #pragma unroll
        for (int n = 0; n < BATCH; n++) {
            float a = 0.f;
            #pragma unroll
            for (int q = 0; q < 4; q++) {
                const float4 xv = *(const float4*)&s_x[n0 + n][fg * 16 + q * 4];
                a += xv.x * w1r[q * 4] + xv.y * w1r[q * 4 + 1]
                   + xv.z * w1r[q * 4 + 2] + xv.w * w1r[q * 4 + 3];
            }
            s_part[fg][n][h] = a;
        }
        __syncthreads();

        #pragma unroll
        for (int k = 0; k < 4; k++) {
            const int p = tid + 256 * k;
            const int n = p >> 6, hh = p & 63;
            const float z = b1[hh] + ((s_part[0][n][hh] + s_part[1][n][hh])
                                    + (s_part[2][n][hh] + s_part[3][n][hh]));
            s_z[n][hh] = fmaxf(z, 0.f);
        }
        __syncthreads();

        #pragma unroll
        for (int n = 0; n < BATCH; n++) {
            float a = 0.f;
            #pragma unroll
            for (int q = 0; q < 4; q++) {
                const float4 zv = *(const float4*)&s_z[n][fg * 16 + q * 4];
                a += zv.x * w2r[q * 4] + zv.y * w2r[q * 4 + 1]
                   + zv.z * w2r[q * 4 + 2] + zv.w * w2r[q * 4 + 3];
            }
            s_part[fg][n][h] = a;
        }
        __syncthreads();

        #pragma unroll
        for (int k = 0; k < 4; k++) {
            const int p = tid + 256 * k;
            const int n = p >> 6, hh = p & 63;
            float v = b2[hh] + ((s_part[0][n][hh] + s_part[1][n][hh])
                              + (s_part[2][n][hh] + s_part[3][n][hh]));
            v = fmaxf(v, 0.f);
            g_h2[(size_t)(base + n0 + n) * HID + hh] = v;
            gacc += gp[base + n0 + n] * v;
        }
        __syncthreads();
    }
    atomicAdd(&s_acc[h], gacc);
    __syncthreads();
    if (tid < HID) atomicAdd(&g_gge[b * HID + tid], s_acc[tid]);
}

// ============================================================================
// Kernel 3: actor MLP + ticket softmax. Dual even/odd accumulator chains
// halve the dependent-FMA critical path in all three matvec loops.
// ============================================================================
#define JPB 8
#define XS  66
__global__ __launch_bounds__(256) void k3_actor(
    const int* __restrict__ cand, const int* __restrict__ mask,
    const float* __restrict__ pmi,
    const float* __restrict__ w1, const float* __restrict__ b1,
    const float* __restrict__ w2, const float* __restrict__ b2,
    const float* __restrict__ w3, const float* __restrict__ b3,
    float* __restrict__ out)
{
    __shared__ __align__(16) float s_w1[HID * HID];
    __shared__ __align__(16) float s_w2[HID * HID];
    __shared__ __align__(16) float s_x[JPB * XS];
    __shared__ float s_bp[4][HID];
    __shared__ float s_base[HID];
    __shared__ float s_red[JJ];
    __shared__ int   s_ticket;

    const int tid  = threadIdx.x;
    const int bb   = blockIdx.x >> 4;
    const int jb0  = (blockIdx.x & 15) * JPB;
    const int job  = tid >> 5;
    const int lane = tid & 31;
    const int h0   = lane * 2;

    {
        const float4* w1v = (const float4*)w1;
        const float4* w2v = (const float4*)w2;
        float4* d1 = (float4*)s_w1; float4* d2 = (float4*)s_w2;
        #pragma unroll
        for (int i = 0; i < 4; i++) {
            cp_async16(&d1[tid + 256 * i], &w1v[tid + 256 * i]);
            cp_async16(&d2[tid + 256 * i], &w2v[tid + 256 * i]);
        }
        cp_commit();
    }

    // batch-invariant base, dual chains
    {
        const int q = tid >> 6, h = tid & 63;
        const float* xs = (q < 2) ? (g_gge + bb * HID) : pmi;
        const int f0 = (q & 1) * 32;
        const int row0 = 64 + (q >> 1) * 64 + f0;
        float ae = 0.f, ao = 0.f;
        #pragma unroll 8
        for (int i = 0; i < 32; i += 2) {
            ae += xs[f0 + i]     * w1[(row0 + i)     * HID + h];
            ao += xs[f0 + i + 1] * w1[(row0 + i + 1) * HID + h];
        }
        s_bp[q][h] = ae + ao;
    }

    {
        const int c = cand[bb * JJ + jb0 + job];
        const float2* e2 = (const float2*)(g_h2 + ((size_t)bb * NN + c) * HID);
        *(float2*)&s_x[job * XS + h0] = e2[lane];
    }
    if (tid == 0) s_ticket = -1;
    cp_wait<0>();
    __syncthreads();

    if (tid < HID)
        s_base[tid] = b1[tid] + ((s_bp[0][tid] + s_bp[1][tid])
                               + (s_bp[2][tid] + s_bp[3][tid]));
    __syncthreads();

    // layer 1: 4 independent chains (2 outputs x even/odd f)
    float a0e = s_base[h0], a1e = s_base[h0 + 1];
    float a0o = 0.f, a1o = 0.f;
    #pragma unroll 16
    for (int f = 0; f < HID; f += 2) {
        const float xe = s_x[job * XS + f];
        const float xo = s_x[job * XS + f + 1];
        const float2 we = *(const float2*)&s_w1[f * HID + h0];
        const float2 wo = *(const float2*)&s_w1[(f + 1) * HID + h0];
        a0e += xe * we.x; a1e += xe * we.y;
        a0o += xo * wo.x; a1o += xo * wo.y;
    }
    __syncthreads();
    s_x[job * XS + h0]     = tanh_fast(a0e + a0o);
    s_x[job * XS + h0 + 1] = tanh_fast(a1e + a1o);
    __syncthreads();

    // layer 2: same 4-chain split
    a0e = b2[h0]; a1e = b2[h0 + 1]; a0o = 0.f; a1o = 0.f;
    #pragma unroll 16
    for (int f = 0; f < HID; f += 2) {
        const float te = s_x[job * XS + f];
        const float to = s_x[job * XS + f + 1];
        const float2 we = *(const float2*)&s_w2[f * HID + h0];
        const float2 wo = *(const float2*)&s_w2[(f + 1) * HID + h0];
        a0e += te * we.x; a1e += te * we.y;
        a0o += to * wo.x; a1o += to * wo.y;
    }

    float part = tanh_fast(a0e + a0o) * w3[h0] + tanh_fast(a1e + a1o) * w3[h0 + 1];
    #pragma unroll
    for (int o = 16; o > 0; o >>= 1)
        part += __shfl_down_sync(0xffffffffu, part, o);
    if (lane == 0) {
        const int jg = jb0 + job;
        float score = (part + b3[0]) * 10.0f;
        if (mask[bb * JJ + jg]) score = -INFINITY;
        g_scores[bb * JJ + jg] = score;
        __threadfence();
    }
    __syncthreads();
    if (tid == 0) s_ticket = atomicAdd(&g_done[bb], 1);
    __syncthreads();

    if (s_ticket == 15) {
        __threadfence();
        const float sc = (tid < JJ) ? __ldcg(&g_scores[bb * JJ + tid]) : -INFINITY;
        if (tid < JJ) s_red[tid] = sc;
        __syncthreads();
        for (int s = JJ / 2; s > 0; s >>= 1) {
            if (tid < s) s_red[tid] = fmaxf(s_red[tid], s_red[tid + s]);
            __syncthreads();
        }
        const float mx = s_red[0]; __syncthreads();
        const float e = (tid < JJ) ? expf(sc - mx) : 0.f;
        if (tid < JJ) s_red[tid] = e;
        __syncthreads();
        for (int s = JJ / 2; s > 0; s >>= 1) {
            if (tid < s) s_red[tid] += s_red[tid + s];
            __syncthreads();
        }
        if (tid < JJ) out[bb * JJ + tid] = e / s_red[0];
    }
}

// ============================================================================
extern "C" void kernel_launch(void* const* d_in, const int* in_sizes, int n_in,
                              void* d_out, int out_size)
{
    const float* features   = (const float*)d_in[0];
    const float* graph_pool = (const float*)d_in[1];
    const float* adj        = (const float*)d_in[2];
    const int*   candidate  = (const int*)d_in[3];
    const int*   mask       = (const int*)d_in[4];
    const float* g0w1 = (const float*)d_in[5];
    const float* g0b1 = (const float*)d_in[6];
    const float* g0w2 = (const float*)d_in[7];
    const float* g0b2 = (const float*)d_in[8];
    const float* g1w1 = (const float*)d_in[9];
    const float* g1b1 = (const float*)d_in[10];
    const float* g1w2 = (const float*)d_in[11];
    const float* g1b2 = (const float*)d_in[12];
    const float* pmi  = (const float*)d_in[13];
    const float* aw1  = (const float*)d_in[14];
    const float* ab1  = (const float*)d_in[15];
    const float* aw2  = (const float*)d_in[16];
    const float* ab2  = (const float*)d_in[17];
    const float* aw3  = (const float*)d_in[18];
    const float* ab3  = (const float*)d_in[19];
    float* out = (float*)d_out;

    k1_scan<<<NROWS / 16, 512>>>(adj, features, g0w1, g0b1, g0w2, g0b2);
    k2_fused<<<NROWS / NPB, 256>>>(g1w1, g1b1, g1w2, g1b2, graph_pool);
    k3_actor<<<BB * JJ / JPB, 256>>>(candidate, mask, pmi,
                                     aw1, ab1, aw2, ab2, aw3, ab3, out);
}

// round 17
// speedup vs baseline: 1.1559x; 1.0142x over previous
#include <cuda_runtime.h>
#include <cstdint>
#include <math.h>

#define BB   8
#define NN   4096
#define HID  64
#define JJ   128
#define CAP  96
#define NROWS (BB*NN)   // 32768

#define NPB   64
#define BATCH 16
#define K2BLK (NROWS / NPB)     // 512 k2 blocks (64 per batch)
#define JPB   8
#define XS    66
#define K3BLK (BB * JJ / JPB)   // 128 k3 blocks (16 per batch)

// ---- scratch (device globals; no allocation allowed) ----
__device__ int   g_cnt[NROWS];
__device__ int   g_idx[(size_t)NROWS * CAP];   // packed: col | (val==2 ? 0x80000000 : 0)
__device__ float g_h1[(size_t)NROWS * HID];    // 8 MB
__device__ float g_h2[(size_t)NROWS * HID];    // 8 MB
__device__ float g_gge[BB * HID];              // global graph embedding accumulator
__device__ float g_scores[BB * JJ];            // actor scores before softmax
__device__ int   g_done[BB];                   // k3 softmax ticket counters
__device__ int   g_k2c[BB];                    // k2 blocks finished per batch

__device__ __forceinline__ void cp_async16(void* smem_dst, const void* gmem_src) {
    unsigned sa = (unsigned)__cvta_generic_to_shared(smem_dst);
    asm volatile("cp.async.cg.shared.global [%0], [%1], 16;\n"
                 :: "r"(sa), "l"(gmem_src));
}
__device__ __forceinline__ void cp_commit() {
    asm volatile("cp.async.commit_group;\n");
}
template <int N>
__device__ __forceinline__ void cp_wait() {
    asm volatile("cp.async.wait_group %0;\n" :: "n"(N));
}
__device__ __forceinline__ float tanh_fast(float x) {
    float r;
    asm("tanh.approx.f32 %0, %1;" : "=f"(r) : "f"(x));
    return r;
}

// ============================================================================
// Kernel 1 (unchanged, at HBM wall): stream adj once via per-warp cp.async
// ring. Warp-per-row, group-skip, shared-atomic compaction + GIN0 MLP.
// 16 rows / 512-thread block. Block 0 resets the k23 handshake counters.
// ============================================================================
#define NBUF 3
#define NCHUNK 32
__global__ __launch_bounds__(512) void k1_scan(
    const float* __restrict__ adj, const float* __restrict__ feat,
    const float* __restrict__ w1, const float* __restrict__ b1,
    const float* __restrict__ w2, const float* __restrict__ b2)
{
    __shared__ float s_w2[HID * HID];
    __shared__ uint4 s_buf[16][NBUF][32];
    __shared__ float s_w1[2 * HID];
    __shared__ float s_b1[HID], s_b2[HID];
    __shared__ float s_p[16][2];
    __shared__ float s_z[16][HID];
    __shared__ int   s_cnt[16];

    const int tid  = threadIdx.x;
    const int w    = tid >> 5;
    const int lane = tid & 31;

    for (int i = tid; i < HID * HID; i += 512) s_w2[i] = w2[i];
    if (tid < 2 * HID) s_w1[tid] = w1[tid];
    if (tid < HID) { s_b1[tid] = b1[tid]; s_b2[tid] = b2[tid]; }
    if (lane == 0) s_cnt[w] = 0;
    if (blockIdx.x == 0) {
        if (tid < BB * HID) g_gge[tid] = 0.f;
        if (tid < BB) { g_done[tid] = 0; g_k2c[tid] = 0; }
    }
    __syncwarp();

    const int r = blockIdx.x * 16 + w;
    const int b = r >> 12;
    const float* __restrict__ grow = adj + (size_t)r * NN;
    const float2* __restrict__ f2p = (const float2*)feat + (size_t)b * NN;
    int* __restrict__ irow = g_idx + (size_t)r * CAP;

    float p0 = 0.f, p1 = 0.f;

#define PROC_ELEM(bits, jj) do {                                           \
        if ((bits) != 0u) {                                                \
            const int pos = atomicAdd(&s_cnt[w], 1);                       \
            const bool two = ((bits) == 0x40000000u);                      \
            if (pos < CAP) irow[pos] = (jj) | (two ? 0x80000000 : 0);      \
            const float2 f = f2p[(jj)];                                    \
            const float sv = two ? 2.f : 1.f;                              \
            p0 += sv * f.x; p1 += sv * f.y;                                \
        }                                                                  \
    } while (0)

#define PROC_CHUNK(c) do {                                                 \
        const uint4 v = s_buf[w][(c) % NBUF][lane];                        \
        if (v.x | v.y | v.z | v.w) {                                       \
            const int jb = (c) * 128 + lane * 4;                           \
            PROC_ELEM(v.x, jb + 0);                                        \
            PROC_ELEM(v.y, jb + 1);                                        \
            PROC_ELEM(v.z, jb + 2);                                        \
            PROC_ELEM(v.w, jb + 3);                                        \
        }                                                                  \
    } while (0)

    #pragma unroll
    for (int c = 0; c < NBUF; c++) {
        cp_async16(&s_buf[w][c][lane], grow + c * 128 + lane * 4);
        cp_commit();
    }
    #pragma unroll 1
    for (int c = 0; c < NCHUNK - NBUF; c++) {
        cp_wait<NBUF - 1>();
        PROC_CHUNK(c);
        cp_async16(&s_buf[w][(c + NBUF) % NBUF][lane],
                   grow + (c + NBUF) * 128 + lane * 4);
        cp_commit();
    }
    cp_wait<0>();
    #pragma unroll
    for (int c = NCHUNK - NBUF; c < NCHUNK; c++) PROC_CHUNK(c);
#undef PROC_CHUNK
#undef PROC_ELEM

    #pragma unroll
    for (int o = 16; o > 0; o >>= 1) {
        p0 += __shfl_down_sync(0xffffffffu, p0, o);
        p1 += __shfl_down_sync(0xffffffffu, p1, o);
    }
    __syncwarp();
    if (lane == 0) {
        s_p[w][0] = p0; s_p[w][1] = p1;
        g_cnt[r] = min(s_cnt[w], CAP);
    }
    __syncthreads();

    const int h = tid & 63;
    const int slot = tid >> 6;
    #pragma unroll
    for (int t = 0; t < 2; t++) {
        const int rr = slot + t * 8;
        const float z = s_b1[h] + s_p[rr][0] * s_w1[h] + s_p[rr][1] * s_w1[HID + h];
        s_z[rr][h] = fmaxf(z, 0.f);
    }
    __syncthreads();
    #pragma unroll
    for (int t = 0; t < 2; t++) {
        const int rr = slot + t * 8;
        float acc = s_b2[h];
        #pragma unroll
        for (int k = 0; k < HID; k++) acc += s_z[rr][k] * s_w2[k * HID + h];
        g_h1[(size_t)(blockIdx.x * 16 + rr) * HID + h] = fmaxf(acc, 0.f);
    }
}

// ---- shared-memory union for the merged k2/k3 kernel ----
struct SK2 {
    float x[NPB][HID];            // 16 KB
    float part[4][BATCH][HID];    // 16 KB
    float z[BATCH][HID];          // 4 KB
    float acc[HID];
};
struct SK3 {
    float w1[HID * HID];          // 16 KB
    float w2[HID * HID];          // 16 KB
    float x[JPB * XS];            // 2.1 KB
    float bp[4][HID];
    float base[HID];
    float red[JJ];
    int   ticket;
};
static constexpr size_t SMEM_MAX =
    sizeof(SK2) > sizeof(SK3) ? sizeof(SK2) : sizeof(SK3);

// ============================================================================
// k2 body (R16 k2_fused + release-increment of g_k2c[batch]).
// ============================================================================
__device__ __forceinline__ void k2_body(
    char* smraw,
    const float* __restrict__ w1, const float* __restrict__ b1,
    const float* __restrict__ w2, const float* __restrict__ b2,
    const float* __restrict__ gp)
{
    SK2& s = *reinterpret_cast<SK2*>(smraw);
    const int tid  = threadIdx.x;
    const int h    = tid & 63;
    const int fg   = tid >> 6;
    const int wid  = tid >> 5, lane = tid & 31;
    const int base = blockIdx.x * NPB;
    const int b    = base >> 12;
    const float2* __restrict__ h1v = (const float2*)g_h1 + ((size_t)b << 12) * 32;

    if (tid < HID) s.acc[tid] = 0.f;

    #pragma unroll 1
    for (int pass = 0; pass < 2; pass++) {
        const int ln0 = wid * 4 + pass * 32;
        int cnt[4]; const int* ip[4];
        #pragma unroll
        for (int i = 0; i < 4; i++) {
            cnt[i] = g_cnt[base + ln0 + i];
            ip[i]  = g_idx + (size_t)(base + ln0 + i) * CAP;
        }
        float ax[4] = {0.f, 0.f, 0.f, 0.f}, ay[4] = {0.f, 0.f, 0.f, 0.f};
        const int maxc = max(max(cnt[0], cnt[1]), max(cnt[2], cnt[3]));
        for (int k0 = 0; k0 < maxc; k0 += 32) {
            int enc[4];
            #pragma unroll
            for (int i = 0; i < 4; i++)
                enc[i] = (k0 + lane < cnt[i]) ? ip[i][k0 + lane] : 0;
            const int rem = min(maxc - k0, 32);
            #pragma unroll 2
            for (int n = 0; n < rem; n++) {
                #pragma unroll
                for (int i = 0; i < 4; i++) {
                    const int e = __shfl_sync(0xffffffffu, enc[i], n);
                    if (k0 + n < cnt[i]) {       // warp-uniform predicate
                        const float2 v = h1v[(size_t)(e & 0x7fffffff) * 32 + lane];
                        const float sv = (e < 0) ? 2.f : 1.f;
                        ax[i] += sv * v.x; ay[i] += sv * v.y;
                    }
                }
            }
        }
        #pragma unroll
        for (int i = 0; i < 4; i++)
            *(float2*)&s.x[ln0 + i][2 * lane] = make_float2(ax[i], ay[i]);
    }

    float w1r[16], w2r[16];
    #pragma unroll
    for (int i = 0; i < 16; i++) {
        w1r[i] = w1[(fg * 16 + i) * HID + h];
        w2r[i] = w2[(fg * 16 + i) * HID + h];
    }
    __syncthreads();

    float gacc = 0.f;
    #pragma unroll 1
    for (int nb = 0; nb < 4; nb++) {
        const int n0 = nb * BATCH;

        #pragma unroll
        for (int n = 0; n < BATCH; n++) {
            float a = 0.f;
            #pragma unroll
            for (int q = 0; q < 4; q++) {
                const float4 xv = *(const float4*)&s.x[n0 + n][fg * 16 + q * 4];
                a += xv.x * w1r[q * 4] + xv.y * w1r[q * 4 + 1]
                   + xv.z * w1r[q * 4 + 2] + xv.w * w1r[q * 4 + 3];
            }
            s.part[fg][n][h] = a;
        }
        __syncthreads();

        #pragma unroll
        for (int k = 0; k < 4; k++) {
            const int p = tid + 256 * k;
            const int n = p >> 6, hh = p & 63;
            const float z = b1[hh] + ((s.part[0][n][hh] + s.part[1][n][hh])
                                    + (s.part[2][n][hh] + s.part[3][n][hh]));
            s.z[n][hh] = fmaxf(z, 0.f);
        }
        __syncthreads();

        #pragma unroll
        for (int n = 0; n < BATCH; n++) {
            float a = 0.f;
            #pragma unroll
            for (int q = 0; q < 4; q++) {
                const float4 zv = *(const float4*)&s.z[n][fg * 16 + q * 4];
                a += zv.x * w2r[q * 4] + zv.y * w2r[q * 4 + 1]
                   + zv.z * w2r[q * 4 + 2] + zv.w * w2r[q * 4 + 3];
            }
            s.part[fg][n][h] = a;
        }
        __syncthreads();

        #pragma unroll
        for (int k = 0; k < 4; k++) {
            const int p = tid + 256 * k;
            const int n = p >> 6, hh = p & 63;
            float v = b2[hh] + ((s.part[0][n][hh] + s.part[1][n][hh])
                              + (s.part[2][n][hh] + s.part[3][n][hh]));
            v = fmaxf(v, 0.f);
            g_h2[(size_t)(base + n0 + n) * HID + hh] = v;
            gacc += gp[base + n0 + n] * v;
        }
        __syncthreads();
    }
    atomicAdd(&s.acc[h], gacc);
    __syncthreads();
    if (tid < HID) atomicAdd(&g_gge[b * HID + tid], s.acc[tid]);
    __syncthreads();
    if (tid == 0) {
        __threadfence();                 // release h2 + gge of this block
        atomicAdd(&g_k2c[b], 1);
    }
}

// ============================================================================
// k3 body: stage actor weights via cp.async BEFORE spinning on the batch
// gate, then run the proven actor MLP + ticket softmax (__ldcg on k2 data).
// ============================================================================
__device__ __forceinline__ void k3_body(
    char* smraw,
    const int* __restrict__ cand, const int* __restrict__ mask,
    const float* __restrict__ pmi,
    const float* __restrict__ w1, const float* __restrict__ b1,
    const float* __restrict__ w2, const float* __restrict__ b2,
    const float* __restrict__ w3, const float* __restrict__ b3,
    float* __restrict__ out)
{
    SK3& s = *reinterpret_cast<SK3*>(smraw);
    const int tid  = threadIdx.x;
    const int bid3 = blockIdx.x - K2BLK;
    const int bb   = bid3 >> 4;
    const int jb0  = (bid3 & 15) * JPB;
    const int job  = tid >> 5;
    const int lane = tid & 31;
    const int h0   = lane * 2;

    // stage weights early: DRAM latency overlaps the spin below
    {
        const float4* w1v = (const float4*)w1;
        const float4* w2v = (const float4*)w2;
        float4* d1 = (float4*)s.w1; float4* d2 = (float4*)s.w2;
        #pragma unroll
        for (int i = 0; i < 4; i++) {
            cp_async16(&d1[tid + 256 * i], &w1v[tid + 256 * i]);
            cp_async16(&d2[tid + 256 * i], &w2v[tid + 256 * i]);
        }
        cp_commit();
    }
    const int c = cand[bb * JJ + jb0 + job];     // input, safe pre-gate
    if (tid == 0) {
        s.ticket = -1;
        while (*(volatile int*)&g_k2c[bb] < 64) __nanosleep(64);
        __threadfence();                 // acquire batch bb's h2 + gge
    }
    __syncthreads();

    // batch-invariant base: b1 + gge@w1[64:128] + pmi@w1[128:192]
    {
        const int q = tid >> 6, h = tid & 63;
        const int f0 = (q & 1) * 32;
        const int row0 = 64 + (q >> 1) * 64 + f0;
        float ae = 0.f, ao = 0.f;
        if (q < 2) {
            #pragma unroll 8
            for (int i = 0; i < 32; i += 2) {
                ae += __ldcg(&g_gge[bb * HID + f0 + i])     * w1[(row0 + i)     * HID + h];
                ao += __ldcg(&g_gge[bb * HID + f0 + i + 1]) * w1[(row0 + i + 1) * HID + h];
            }
        } else {
            #pragma unroll 8
            for (int i = 0; i < 32; i += 2) {
                ae += pmi[f0 + i]     * w1[(row0 + i)     * HID + h];
                ao += pmi[f0 + i + 1] * w1[(row0 + i + 1) * HID + h];
            }
        }
        s.bp[q][h] = ae + ao;
    }

    // candidate embeddings (k2 output -> __ldcg)
    {
        const float2* e2 = (const float2*)(g_h2 + ((size_t)bb * NN + c) * HID);
        *(float2*)&s.x[job * XS + h0] = __ldcg(&e2[lane]);
    }
    cp_wait<0>();
    __syncthreads();

    if (tid < HID)
        s.base[tid] = b1[tid] + ((s.bp[0][tid] + s.bp[1][tid])
                               + (s.bp[2][tid] + s.bp[3][tid]));
    __syncthreads();

    // layer 1
    float a0e = s.base[h0], a1e = s.base[h0 + 1];
    float a0o = 0.f, a1o = 0.f;
    #pragma unroll 16
    for (int f = 0; f < HID; f += 2) {
        const float xe = s.x[job * XS + f];
        const float xo = s.x[job * XS + f + 1];
        const float2 we = *(const float2*)&s.w1[f * HID + h0];
        const float2 wo = *(const float2*)&s.w1[(f + 1) * HID + h0];
        a0e += xe * we.x; a1e += xe * we.y;
        a0o += xo * wo.x; a1o += xo * wo.y;
    }
    __syncthreads();
    s.x[job * XS + h0]     = tanh_fast(a0e + a0o);
    s.x[job * XS + h0 + 1] = tanh_fast(a1e + a1o);
    __syncthreads();

    // layer 2
    a0e = b2[h0]; a1e = b2[h0 + 1]; a0o = 0.f; a1o = 0.f;
    #pragma unroll 16
    for (int f = 0; f < HID; f += 2) {
        const float te = s.x[job * XS + f];
        const float to = s.x[job * XS + f + 1];
        const float2 we = *(const float2*)&s.w2[f * HID + h0];
        const float2 wo = *(const float2*)&s.w2[(f + 1) * HID + h0];
        a0e += te * we.x; a1e += te * we.y;
        a0o += to * wo.x; a1o += to * wo.y;
    }

    float part = tanh_fast(a0e + a0o) * w3[h0] + tanh_fast(a1e + a1o) * w3[h0 + 1];
    #pragma unroll
    for (int o = 16; o > 0; o >>= 1)
        part += __shfl_down_sync(0xffffffffu, part, o);
    if (lane == 0) {
        const int jg = jb0 + job;
        float score = (part + b3[0]) * 10.0f;
        if (mask[bb * JJ + jg]) score = -INFINITY;
        g_scores[bb * JJ + jg] = score;
        __threadfence();
    }
    __syncthreads();
    if (tid == 0) s.ticket = atomicAdd(&g_done[bb], 1);
    __syncthreads();

    if (s.ticket == 15) {                // last of 16 k3 blocks for this batch
        __threadfence();
        const float sc = (tid < JJ) ? __ldcg(&g_scores[bb * JJ + tid]) : -INFINITY;
        if (tid < JJ) s.red[tid] = sc;
        __syncthreads();
        for (int st = JJ / 2; st > 0; st >>= 1) {
            if (tid < st) s.red[tid] = fmaxf(s.red[tid], s.red[tid + st]);
            __syncthreads();
        }
        const float mx = s.red[0]; __syncthreads();
        const float e = (tid < JJ) ? expf(sc - mx) : 0.f;
        if (tid < JJ) s.red[tid] = e;
        __syncthreads();
        for (int st = JJ / 2; st > 0; st >>= 1) {
            if (tid < st) s.red[tid] += s.red[tid + st];
            __syncthreads();
        }
        if (tid < JJ) out[bb * JJ + tid] = e / s.red[0];
    }
}

// ============================================================================
// Merged kernel: blocks [0,512) = k2 tiles; [512,640) = gated k3 blocks.
// ============================================================================
__global__ __launch_bounds__(256) void k23(
    const float* __restrict__ c_w1, const float* __restrict__ c_b1,
    const float* __restrict__ c_w2, const float* __restrict__ c_b2,
    const float* __restrict__ gp,
    const int* __restrict__ cand, const int* __restrict__ mask,
    const float* __restrict__ pmi,
    const float* __restrict__ a_w1, const float* __restrict__ a_b1,
    const float* __restrict__ a_w2, const float* __restrict__ a_b2,
    const float* __restrict__ a_w3, const float* __restrict__ a_b3,
    float* __restrict__ out)
{
    __shared__ __align__(16) char smraw[SMEM_MAX];
    if (blockIdx.x < K2BLK)
        k2_body(smraw, c_w1, c_b1, c_w2, c_b2, gp);
    else
        k3_body(smraw, cand, mask, pmi, a_w1, a_b1, a_w2, a_b2, a_w3, a_b3, out);
}

// ============================================================================
extern "C" void kernel_launch(void* const* d_in, const int* in_sizes, int n_in,
                              void* d_out, int out_size)
{
    const float* features   = (const float*)d_in[0];
    const float* graph_pool = (const float*)d_in[1];
    const float* adj        = (const float*)d_in[2];
    const int*   candidate  = (const int*)d_in[3];
    const int*   mask       = (const int*)d_in[4];
    const float* g0w1 = (const float*)d_in[5];
    const float* g0b1 = (const float*)d_in[6];
    const float* g0w2 = (const float*)d_in[7];
    const float* g0b2 = (const float*)d_in[8];
    const float* g1w1 = (const float*)d_in[9];
    const float* g1b1 = (const float*)d_in[10];
    const float* g1w2 = (const float*)d_in[11];
    const float* g1b2 = (const float*)d_in[12];
    const float* pmi  = (const float*)d_in[13];
    const float* aw1  = (const float*)d_in[14];
    const float* ab1  = (const float*)d_in[15];
    const float* aw2  = (const float*)d_in[16];
    const float* ab2  = (const float*)d_in[17];
    const float* aw3  = (const float*)d_in[18];
    const float* ab3  = (const float*)d_in[19];
    float* out = (float*)d_out;

    k1_scan<<<NROWS / 16, 512>>>(adj, features, g0w1, g0b1, g0w2, g0b2);
    k23<<<K2BLK + K3BLK, 256>>>(g1w1, g1b1, g1w2, g1b2, graph_pool,
                                candidate, mask, pmi,
                                aw1, ab1, aw2, ab2, aw3, ab3, out);
}